// round 6
// baseline (speedup 1.0000x reference)
#include <cuda_runtime.h>
#include <cuda_bf16.h>
#include <math.h>
#include <stdint.h>

#define B_  2
#define T_  2048
#define D_  2048
#define H_  16
#define G_  4
#define DK_ 128
#define MT  (B_*T_)          // 4096 rows
#define KVW (G_*DK_)         // 512

// ---------------------------------------------------------------------------
// Scratch (device globals: allocation-free rule)
// ---------------------------------------------------------------------------
__device__ float g_q[(size_t)MT * D_];
__device__ float g_k[(size_t)MT * KVW];
__device__ float g_v[(size_t)MT * KVW];

__device__ __nv_bfloat16 g_xh[(size_t)MT * D_];
__device__ __nv_bfloat16 g_xl[(size_t)MT * D_];
__device__ __nv_bfloat16 g_yh[(size_t)MT * D_];
__device__ __nv_bfloat16 g_yl[(size_t)MT * D_];
__device__ __nv_bfloat16 g_qh[(size_t)MT * D_];
__device__ __nv_bfloat16 g_ql[(size_t)MT * D_];
__device__ __nv_bfloat16 g_kh[(size_t)MT * KVW];
__device__ __nv_bfloat16 g_kl[(size_t)MT * KVW];
__device__ __nv_bfloat16 g_vh[(size_t)MT * KVW];
__device__ __nv_bfloat16 g_vl[(size_t)MT * KVW];
// transposed weights [N][K] bf16
__device__ __nv_bfloat16 g_wqh[(size_t)D_ * D_];
__device__ __nv_bfloat16 g_wql[(size_t)D_ * D_];
__device__ __nv_bfloat16 g_wkh[(size_t)KVW * D_];
__device__ __nv_bfloat16 g_wkl[(size_t)KVW * D_];
__device__ __nv_bfloat16 g_wvh[(size_t)KVW * D_];
__device__ __nv_bfloat16 g_wvl[(size_t)KVW * D_];
__device__ __nv_bfloat16 g_woh[(size_t)D_ * D_];
__device__ __nv_bfloat16 g_wol[(size_t)D_ * D_];

// ---------------------------------------------------------------------------
// Portable PTX helpers (valid at compute_103, no 'a' features)
// ---------------------------------------------------------------------------
__device__ __forceinline__ uint32_t smem_u32(const void* p) {
    uint32_t a;
    asm("{ .reg .u64 t; cvta.to.shared.u64 t, %1; cvt.u32.u64 %0, t; }" : "=r"(a) : "l"(p));
    return a;
}
__device__ __forceinline__ void cp16(uint32_t dst, const void* src) {
    asm volatile("cp.async.cg.shared.global [%0], [%1], 16;" :: "r"(dst), "l"(src));
}
#define CP_COMMIT() asm volatile("cp.async.commit_group;" ::: "memory")
#define CP_WAIT1()  asm volatile("cp.async.wait_group 1;" ::: "memory")
#define CP_WAIT0()  asm volatile("cp.async.wait_group 0;" ::: "memory")

__device__ __forceinline__ void ldm_x4(uint32_t* r, uint32_t addr) {
    asm volatile("ldmatrix.sync.aligned.m8n8.x4.shared.b16 {%0,%1,%2,%3}, [%4];"
                 : "=r"(r[0]), "=r"(r[1]), "=r"(r[2]), "=r"(r[3]) : "r"(addr));
}
__device__ __forceinline__ void ldm_x4t(uint32_t* r, uint32_t addr) {
    asm volatile("ldmatrix.sync.aligned.m8n8.x4.trans.shared.b16 {%0,%1,%2,%3}, [%4];"
                 : "=r"(r[0]), "=r"(r[1]), "=r"(r[2]), "=r"(r[3]) : "r"(addr));
}
__device__ __forceinline__ void mma16816(float* d, const uint32_t* a,
                                         uint32_t b0, uint32_t b1) {
    asm volatile("mma.sync.aligned.m16n8k16.row.col.f32.bf16.bf16.f32 "
                 "{%0,%1,%2,%3}, {%4,%5,%6,%7}, {%8,%9}, {%0,%1,%2,%3};"
                 : "+f"(d[0]), "+f"(d[1]), "+f"(d[2]), "+f"(d[3])
                 : "r"(a[0]), "r"(a[1]), "r"(a[2]), "r"(a[3]), "r"(b0), "r"(b1));
}
__device__ __forceinline__ uint32_t pack_bf16(float f0, float f1) {
    __nv_bfloat162 h = __floats2bfloat162_rn(f0, f1);
    return *(uint32_t*)&h;
}

// ---------------------------------------------------------------------------
// fp32 -> bf16 hi/lo split (elementwise)
// ---------------------------------------------------------------------------
__global__ void split_bf16(const float* __restrict__ in, __nv_bfloat16* __restrict__ hi,
                           __nv_bfloat16* __restrict__ lo, int n4)
{
    int i = blockIdx.x * blockDim.x + threadIdx.x;
    if (i >= n4) return;
    float4 v = ((const float4*)in)[i];
    __nv_bfloat16 h0 = __float2bfloat16(v.x), h1 = __float2bfloat16(v.y);
    __nv_bfloat16 h2 = __float2bfloat16(v.z), h3 = __float2bfloat16(v.w);
    __nv_bfloat16 l0 = __float2bfloat16(v.x - __bfloat162float(h0));
    __nv_bfloat16 l1 = __float2bfloat16(v.y - __bfloat162float(h1));
    __nv_bfloat16 l2 = __float2bfloat16(v.z - __bfloat162float(h2));
    __nv_bfloat16 l3 = __float2bfloat16(v.w - __bfloat162float(h3));
    ((__nv_bfloat162*)hi)[i * 2]     = __nv_bfloat162(h0, h1);
    ((__nv_bfloat162*)hi)[i * 2 + 1] = __nv_bfloat162(h2, h3);
    ((__nv_bfloat162*)lo)[i * 2]     = __nv_bfloat162(l0, l1);
    ((__nv_bfloat162*)lo)[i * 2 + 1] = __nv_bfloat162(l2, l3);
}

// ---------------------------------------------------------------------------
// RoPE + split: read fp32 [B*T][nh*128], rotate pairs (i, i+64), write hi/lo.
// ---------------------------------------------------------------------------
__global__ void rope_split(const float* __restrict__ src, __nv_bfloat16* __restrict__ hi,
                           __nv_bfloat16* __restrict__ lo, int nh)
{
    int idx = blockIdx.x * blockDim.x + threadIdx.x;
    int total = MT * nh * 64;
    if (idx >= total) return;
    int i   = idx & 63;
    int h   = (idx >> 6) % nh;
    int row = idx / (64 * nh);
    int t   = row & (T_ - 1);
    float inv = powf(10000.f, -(float)i * (1.f / 64.f));
    float ang = (float)t * inv;
    float s, c;
    sincosf(ang, &s, &c);
    size_t base = (size_t)row * nh * DK_ + h * DK_;
    float x1 = src[base + i], x2 = src[base + i + 64];
    float r1 = x1 * c - x2 * s;
    float r2 = x2 * c + x1 * s;
    __nv_bfloat16 h1 = __float2bfloat16(r1);
    __nv_bfloat16 h2 = __float2bfloat16(r2);
    hi[base + i]      = h1;
    hi[base + i + 64] = h2;
    lo[base + i]      = __float2bfloat16(r1 - __bfloat162float(h1));
    lo[base + i + 64] = __float2bfloat16(r2 - __bfloat162float(h2));
}

// ---------------------------------------------------------------------------
// W[K][N] fp32 -> Wt_hi/lo[N][K] bf16 (transpose + split)
// ---------------------------------------------------------------------------
__global__ void tsplit_bf16(const float* __restrict__ W, __nv_bfloat16* __restrict__ Th,
                            __nv_bfloat16* __restrict__ Tl, int K, int N)
{
    __shared__ float t[32][33];
    int n0 = blockIdx.x * 32, k0 = blockIdx.y * 32;
    int tx = threadIdx.x, ty = threadIdx.y;
#pragma unroll
    for (int i = 0; i < 4; i++)
        t[ty + i * 8][tx] = W[(size_t)(k0 + ty + i * 8) * N + n0 + tx];
    __syncthreads();
#pragma unroll
    for (int i = 0; i < 4; i++) {
        float v = t[tx][ty + i * 8];
        __nv_bfloat16 h = __float2bfloat16(v);
        __nv_bfloat16 l = __float2bfloat16(v - __bfloat162float(h));
        size_t o = (size_t)(n0 + ty + i * 8) * K + k0 + tx;
        Th[o] = h;
        Tl[o] = l;
    }
}

// ---------------------------------------------------------------------------
// HMMA GEMM: C = (Ah+Al)(Bh+Bl)^T, 3-term. Term-major MMA ordering so no
// back-to-back MMAs share an accumulator (HMMA latency > issue rate).
// ---------------------------------------------------------------------------
#define GT_TILE  16384u
#define GT_STAGE 65536u
#define GEMM_SMEM (2 * 65536 + 128)

__global__ __launch_bounds__(256) void gemm_hmma_x3(
    const __nv_bfloat16* __restrict__ Ah, const __nv_bfloat16* __restrict__ Al,
    const __nv_bfloat16* __restrict__ Bh, const __nv_bfloat16* __restrict__ Bl,
    float* __restrict__ C, int M, int N, int Kd)
{
    extern __shared__ __align__(128) char dsm[];
    uint32_t dbase = smem_u32(dsm);
    const uint32_t base = (dbase + 127u) & ~127u;

    const int tid  = threadIdx.x;
    const int lane = tid & 31;
    const int w    = tid >> 5;
    const int wm   = w & 1;
    const int wn   = w >> 1;
    const int m0   = blockIdx.y * 128, n0 = blockIdx.x * 128;

    const __nv_bfloat16* srcs[4] = { Ah, Al, Bh, Bl };
    const int rowb[4] = { m0, m0, n0, n0 };

    float d[4][4][4];
#pragma unroll
    for (int mi = 0; mi < 4; mi++)
#pragma unroll
        for (int ni = 0; ni < 4; ni++)
#pragma unroll
            for (int r = 0; r < 4; r++) d[mi][ni][r] = 0.f;

    const int NC = Kd / 64;

    auto load_stage = [&](int buf, int k0) {
        uint32_t sb = base + (uint32_t)buf * GT_STAGE;
#pragma unroll
        for (int t = 0; t < 4; t++) {
            const __nv_bfloat16* gp = srcs[t] + (size_t)rowb[t] * Kd + k0;
#pragma unroll
            for (int i = 0; i < 4; i++) {
                int id = tid + i * 256;
                int r = id >> 3, cc = id & 7;
                uint32_t dst = sb + t * GT_TILE +
                               (uint32_t)(r * 128 + ((cc ^ (r & 7)) << 4));
                cp16(dst, gp + (size_t)r * Kd + cc * 8);
            }
        }
    };

    load_stage(0, 0);
    CP_COMMIT();

    for (int c = 0; c < NC; c++) {
        if (c + 1 < NC) {
            load_stage((c + 1) & 1, (c + 1) * 64);
            CP_COMMIT();
            CP_WAIT1();
        } else {
            CP_WAIT0();
        }
        __syncthreads();

        const uint32_t sb = base + (uint32_t)(c & 1) * GT_STAGE;

        const int arow = wm * 64 + (lane & 15);
        const int akc0 = (lane >> 4);
        const int asw  = arow & 7;
        const int brow = wn * 32 + (lane & 7) + ((lane >> 4) & 1) * 8;
        const int bkc0 = ((lane >> 3) & 1);
        const int bsw  = brow & 7;

#pragma unroll
        for (int ks = 0; ks < 4; ks++) {
            uint32_t af[2][4][4];
            uint32_t bf[2][2][4];
            const int akc = ks * 2 + akc0;
            const uint32_t aoff = (uint32_t)(arow * 128 + ((akc ^ asw) << 4));
#pragma unroll
            for (int term = 0; term < 2; term++) {
                uint32_t tb = sb + (uint32_t)term * GT_TILE + aoff;
#pragma unroll
                for (int mi = 0; mi < 4; mi++)
                    ldm_x4(af[term][mi], tb + (uint32_t)mi * 2048);
            }
            const int bkc = ks * 2 + bkc0;
            const uint32_t boff = (uint32_t)(brow * 128 + ((bkc ^ bsw) << 4));
#pragma unroll
            for (int term = 0; term < 2; term++) {
                uint32_t tb = sb + 2 * GT_TILE + (uint32_t)term * GT_TILE + boff;
#pragma unroll
                for (int np = 0; np < 2; np++)
                    ldm_x4(bf[term][np], tb + (uint32_t)np * 2048);
            }
            // term-major: 16 distinct accumulators between reuses
#pragma unroll
            for (int mi = 0; mi < 4; mi++)
#pragma unroll
                for (int ni = 0; ni < 4; ni++) {
                    const int bi = ni >> 1, rs = (ni & 1) * 2;
                    mma16816(d[mi][ni], af[0][mi], bf[0][bi][rs], bf[0][bi][rs + 1]);
                }
#pragma unroll
            for (int mi = 0; mi < 4; mi++)
#pragma unroll
                for (int ni = 0; ni < 4; ni++) {
                    const int bi = ni >> 1, rs = (ni & 1) * 2;
                    mma16816(d[mi][ni], af[0][mi], bf[1][bi][rs], bf[1][bi][rs + 1]);
                }
#pragma unroll
            for (int mi = 0; mi < 4; mi++)
#pragma unroll
                for (int ni = 0; ni < 4; ni++) {
                    const int bi = ni >> 1, rs = (ni & 1) * 2;
                    mma16816(d[mi][ni], af[1][mi], bf[0][bi][rs], bf[0][bi][rs + 1]);
                }
        }
        __syncthreads();
    }

    const int mb = m0 + wm * 64;
    const int nb = n0 + wn * 32;
#pragma unroll
    for (int mi = 0; mi < 4; mi++) {
#pragma unroll
        for (int ni = 0; ni < 4; ni++) {
            int r0 = mb + mi * 16 + (lane >> 2);
            int cc = nb + ni * 8 + (lane & 3) * 2;
            *(float2*)&C[(size_t)r0 * N + cc] = make_float2(d[mi][ni][0], d[mi][ni][1]);
            *(float2*)&C[(size_t)(r0 + 8) * N + cc] = make_float2(d[mi][ni][2], d[mi][ni][3]);
        }
    }
}

// ---------------------------------------------------------------------------
// HMMA flash attention, bf16x3, double-buffered K/V, reversed CTA order.
// Smem: Q 64KB + K 2stages x 32KB + V 2stages x 32KB = 192KB.
// ---------------------------------------------------------------------------
#define AT_SMEM (65536 + 65536 + 65536)

__global__ __launch_bounds__(256) void attn_hmma(
    const __nv_bfloat16* __restrict__ qh, const __nv_bfloat16* __restrict__ ql,
    const __nv_bfloat16* __restrict__ kh, const __nv_bfloat16* __restrict__ kl,
    const __nv_bfloat16* __restrict__ vh, const __nv_bfloat16* __restrict__ vl,
    __nv_bfloat16* __restrict__ yh, __nv_bfloat16* __restrict__ yl)
{
    extern __shared__ __align__(128) char dsm[];
    const uint32_t sQ = smem_u32(dsm);           // 2 x 32768 (hi, lo)
    const uint32_t sK = sQ + 65536;              // 2 stages x (hi 16K + lo 16K)
    const uint32_t sV = sK + 65536;

    const int tid = threadIdx.x, lane = tid & 31, w = tid >> 5;
    const int q0 = (gridDim.x - 1 - blockIdx.x) * 128;   // heavy CTAs first
    const int h  = blockIdx.y;
    const int b  = blockIdx.z;
    const int g  = h >> 2;
    const float scale = 0.08838834764831845f;

    // ---- load Q tile (hi, lo) ----
    const __nv_bfloat16* qsrc[2] = {
        qh + ((size_t)(b * T_ + q0)) * D_ + h * DK_,
        ql + ((size_t)(b * T_ + q0)) * D_ + h * DK_ };
#pragma unroll
    for (int term = 0; term < 2; term++)
#pragma unroll
        for (int it = 0; it < 8; it++) {
            int slot = tid + it * 256;
            int r = slot >> 4, ch = slot & 15;
            uint32_t dst = sQ + term * 32768 + (uint32_t)(r * 256 + ((ch ^ (r & 7)) << 4));
            cp16(dst, qsrc[term] + (size_t)r * D_ + ch * 8);
        }
    CP_COMMIT();

    const __nv_bfloat16* ksrc[2] = {
        kh + ((size_t)(b * T_)) * KVW + g * DK_,
        kl + ((size_t)(b * T_)) * KVW + g * DK_ };
    const __nv_bfloat16* vsrc[2] = {
        vh + ((size_t)(b * T_)) * KVW + g * DK_,
        vl + ((size_t)(b * T_)) * KVW + g * DK_ };

    auto load_kv = [&](int stage, int j0) {
        uint32_t kb = sK + (uint32_t)stage * 32768;
        uint32_t vb = sV + (uint32_t)stage * 32768;
#pragma unroll
        for (int term = 0; term < 2; term++)
#pragma unroll
            for (int it = 0; it < 4; it++) {
                int slot = tid + it * 256;
                int r = slot >> 4, ch = slot & 15;
                uint32_t so = (uint32_t)(r * 256 + ((ch ^ (r & 7)) << 4));
                cp16(kb + term * 16384 + so, ksrc[term] + (size_t)(j0 + r) * KVW + ch * 8);
                cp16(vb + term * 16384 + so, vsrc[term] + (size_t)(j0 + r) * KVW + ch * 8);
            }
    };

    float o[16][4];
#pragma unroll
    for (int ni = 0; ni < 16; ni++)
#pragma unroll
        for (int r = 0; r < 4; r++) o[ni][r] = 0.f;
    float m_run[2] = { -INFINITY, -INFINITY };
    float l_run[2] = { 0.f, 0.f };

    const int nt = q0 / 64 + 2;    // causal: k-tiles 0 .. nt-1

    const int arow = w * 16 + (lane & 15);
    const int akc0 = lane >> 4;
    const int asw  = arow & 7;
    const int kbrow_l = (lane & 7) + ((lane >> 4) & 1) * 8;
    const int kbkc0   = (lane >> 3) & 1;
    const int vrow_l  = (lane & 7) + ((lane >> 3) & 1) * 8;
    const int vnc0    = lane >> 4;

    load_kv(0, 0);
    CP_COMMIT();

    for (int jt = 0; jt < nt; jt++) {
        const int cur = jt & 1;
        if (jt > 0) __syncthreads();   // prev compute done with stage being reloaded
        if (jt + 1 < nt) {
            load_kv(1 - cur, (jt + 1) * 64);
            CP_COMMIT();
            CP_WAIT1();
        } else {
            CP_WAIT0();
        }
        __syncthreads();

        const uint32_t sKs = sK + (uint32_t)cur * 32768;
        const uint32_t sVs = sV + (uint32_t)cur * 32768;
        const int j0 = jt * 64;

        // ---- S = Q K^T (3-term, term-major) ----
        float s[8][4];
#pragma unroll
        for (int ni = 0; ni < 8; ni++)
#pragma unroll
            for (int r = 0; r < 4; r++) s[ni][r] = 0.f;

#pragma unroll
        for (int ks = 0; ks < 8; ks++) {
            uint32_t aq[2][4];
            const int akc = ks * 2 + akc0;
            const uint32_t aoff = (uint32_t)(arow * 256 + ((akc ^ asw) << 4));
            ldm_x4(aq[0], sQ + aoff);
            ldm_x4(aq[1], sQ + 32768 + aoff);
            uint32_t bk[2][4][4];
            const int bkc = ks * 2 + kbkc0;
#pragma unroll
            for (int nc = 0; nc < 4; nc++) {
                const int br = nc * 16 + kbrow_l;
                const uint32_t boff = (uint32_t)(br * 256 + ((bkc ^ (br & 7)) << 4));
                ldm_x4(bk[0][nc], sKs + boff);
                ldm_x4(bk[1][nc], sKs + 16384 + boff);
            }
#pragma unroll
            for (int ni = 0; ni < 8; ni++) {
                const int grp = ni >> 1, rs = (ni & 1) * 2;
                mma16816(s[ni], aq[0], bk[0][grp][rs], bk[0][grp][rs + 1]);
            }
#pragma unroll
            for (int ni = 0; ni < 8; ni++) {
                const int grp = ni >> 1, rs = (ni & 1) * 2;
                mma16816(s[ni], aq[0], bk[1][grp][rs], bk[1][grp][rs + 1]);
            }
#pragma unroll
            for (int ni = 0; ni < 8; ni++) {
                const int grp = ni >> 1, rs = (ni & 1) * 2;
                mma16816(s[ni], aq[1], bk[0][grp][rs], bk[0][grp][rs + 1]);
            }
        }

        // ---- scale + causal mask ----
        const bool needmask = (jt >= nt - 2);
        const int rbase = q0 + w * 16 + (lane >> 2);
        const int cbase = j0 + (lane & 3) * 2;
#pragma unroll
        for (int ni = 0; ni < 8; ni++)
#pragma unroll
            for (int r = 0; r < 4; r++) {
                float val = s[ni][r] * scale;
                if (needmask) {
                    int row = rbase + (r >> 1) * 8;
                    int col = cbase + ni * 8 + (r & 1);
                    if (col > row) val = -INFINITY;
                }
                s[ni][r] = val;
            }

        // ---- online softmax ----
        float alpha[2];
#pragma unroll
        for (int rr = 0; rr < 2; rr++) {
            float mx = -INFINITY;
#pragma unroll
            for (int ni = 0; ni < 8; ni++)
                mx = fmaxf(mx, fmaxf(s[ni][rr * 2], s[ni][rr * 2 + 1]));
            mx = fmaxf(mx, __shfl_xor_sync(0xffffffffu, mx, 1));
            mx = fmaxf(mx, __shfl_xor_sync(0xffffffffu, mx, 2));
            float m_new = fmaxf(m_run[rr], mx);
            alpha[rr] = __expf(m_run[rr] - m_new);
            float sum = 0.f;
#pragma unroll
            for (int ni = 0; ni < 8; ni++) {
                float p0 = __expf(s[ni][rr * 2]     - m_new);
                float p1 = __expf(s[ni][rr * 2 + 1] - m_new);
                s[ni][rr * 2]     = p0;
                s[ni][rr * 2 + 1] = p1;
                sum += p0 + p1;
            }
            sum += __shfl_xor_sync(0xffffffffu, sum, 1);
            sum += __shfl_xor_sync(0xffffffffu, sum, 2);
            l_run[rr] = l_run[rr] * alpha[rr] + sum;
            m_run[rr] = m_new;
        }
#pragma unroll
        for (int ni = 0; ni < 16; ni++) {
            o[ni][0] *= alpha[0]; o[ni][1] *= alpha[0];
            o[ni][2] *= alpha[1]; o[ni][3] *= alpha[1];
        }

        // ---- O += P V (3-term, nc-pair interleave) ----
#pragma unroll
        for (int kk = 0; kk < 4; kk++) {
            uint32_t pa_h[4], pa_l[4];
#pragma unroll
            for (int half = 0; half < 2; half++) {
                const float* sp = s[2 * kk + half];
#pragma unroll
                for (int rr = 0; rr < 2; rr++) {
                    float f0 = sp[rr * 2], f1 = sp[rr * 2 + 1];
                    __nv_bfloat16 h0 = __float2bfloat16(f0);
                    __nv_bfloat16 h1 = __float2bfloat16(f1);
                    __nv_bfloat162 t2(h0, h1);
                    pa_h[half * 2 + rr] = *(uint32_t*)&t2;
                    pa_l[half * 2 + rr] = pack_bf16(f0 - __bfloat162float(h0),
                                                    f1 - __bfloat162float(h1));
                }
            }
            const int vr = kk * 16 + vrow_l;
#pragma unroll
            for (int ncp = 0; ncp < 4; ncp++) {
                uint32_t bv[2][2][4];   // [term][nc2][frag]
#pragma unroll
                for (int nc2 = 0; nc2 < 2; nc2++) {
                    const int nc = ncp * 2 + nc2;
                    const int vch = nc * 2 + vnc0;
                    const uint32_t voff = (uint32_t)(vr * 256 + ((vch ^ (vr & 7)) << 4));
                    ldm_x4t(bv[0][nc2], sVs + voff);
                    ldm_x4t(bv[1][nc2], sVs + 16384 + voff);
                }
                // 3 term-groups of 4 MMAs, all 4 distinct accumulators
#pragma unroll
                for (int nc2 = 0; nc2 < 2; nc2++) {
                    const int nc = ncp * 2 + nc2;
                    mma16816(o[2 * nc],     pa_h, bv[0][nc2][0], bv[0][nc2][1]);
                    mma16816(o[2 * nc + 1], pa_h, bv[0][nc2][2], bv[0][nc2][3]);
                }
#pragma unroll
                for (int nc2 = 0; nc2 < 2; nc2++) {
                    const int nc = ncp * 2 + nc2;
                    mma16816(o[2 * nc],     pa_h, bv[1][nc2][0], bv[1][nc2][1]);
                    mma16816(o[2 * nc + 1], pa_h, bv[1][nc2][2], bv[1][nc2][3]);
                }
#pragma unroll
                for (int nc2 = 0; nc2 < 2; nc2++) {
                    const int nc = ncp * 2 + nc2;
                    mma16816(o[2 * nc],     pa_l, bv[0][nc2][0], bv[0][nc2][1]);
                    mma16816(o[2 * nc + 1], pa_l, bv[0][nc2][2], bv[0][nc2][3]);
                }
            }
        }
    }

    // ---- epilogue: O / l, write bf16 hi/lo ----
    const int rowg = b * T_ + q0 + w * 16 + (lane >> 2);
    const int colg = h * DK_ + (lane & 3) * 2;
#pragma unroll
    for (int rr = 0; rr < 2; rr++) {
        float inv = 1.f / l_run[rr];
        size_t rb = (size_t)(rowg + rr * 8) * D_ + colg;
#pragma unroll
        for (int ni = 0; ni < 16; ni++) {
            float f0 = o[ni][rr * 2] * inv;
            float f1 = o[ni][rr * 2 + 1] * inv;
            __nv_bfloat16 h0 = __float2bfloat16(f0);
            __nv_bfloat16 h1 = __float2bfloat16(f1);
            *(__nv_bfloat162*)&yh[rb + ni * 8] = __nv_bfloat162(h0, h1);
            *(__nv_bfloat162*)&yl[rb + ni * 8] =
                __nv_bfloat162(__float2bfloat16(f0 - __bfloat162float(h0)),
                               __float2bfloat16(f1 - __bfloat162float(h1)));
        }
    }
}

// ---------------------------------------------------------------------------
extern "C" void kernel_launch(void* const* d_in, const int* in_sizes, int n_in,
                              void* d_out, int out_size)
{
    const float* x  = (const float*)d_in[0];
    const float* Wq = (const float*)d_in[1];
    const float* Wk = (const float*)d_in[2];
    const float* Wv = (const float*)d_in[3];
    const float* Wo = (const float*)d_in[4];
    float* out = (float*)d_out;

    float *q, *k, *v;
    cudaGetSymbolAddress((void**)&q, g_q);
    cudaGetSymbolAddress((void**)&k, g_k);
    cudaGetSymbolAddress((void**)&v, g_v);
    __nv_bfloat16 *xh, *xl, *yh, *yl, *qh, *ql, *kvh, *kvl, *vvh, *vvl;
    __nv_bfloat16 *wqh, *wql, *wkh, *wkl, *wvh, *wvl, *woh, *wol;
    cudaGetSymbolAddress((void**)&xh, g_xh);   cudaGetSymbolAddress((void**)&xl, g_xl);
    cudaGetSymbolAddress((void**)&yh, g_yh);   cudaGetSymbolAddress((void**)&yl, g_yl);
    cudaGetSymbolAddress((void**)&qh, g_qh);   cudaGetSymbolAddress((void**)&ql, g_ql);
    cudaGetSymbolAddress((void**)&kvh, g_kh);  cudaGetSymbolAddress((void**)&kvl, g_kl);
    cudaGetSymbolAddress((void**)&vvh, g_vh);  cudaGetSymbolAddress((void**)&vvl, g_vl);
    cudaGetSymbolAddress((void**)&wqh, g_wqh); cudaGetSymbolAddress((void**)&wql, g_wql);
    cudaGetSymbolAddress((void**)&wkh, g_wkh); cudaGetSymbolAddress((void**)&wkl, g_wkl);
    cudaGetSymbolAddress((void**)&wvh, g_wvh); cudaGetSymbolAddress((void**)&wvl, g_wvl);
    cudaGetSymbolAddress((void**)&woh, g_woh); cudaGetSymbolAddress((void**)&wol, g_wol);

    cudaFuncSetAttribute(gemm_hmma_x3, cudaFuncAttributeMaxDynamicSharedMemorySize, GEMM_SMEM);
    cudaFuncSetAttribute(attn_hmma, cudaFuncAttributeMaxDynamicSharedMemorySize, AT_SMEM);

    // Split inputs to bf16 hi/lo
    {
        int n4 = (MT * D_) / 4;
        split_bf16<<<(n4 + 255) / 256, 256>>>(x, xh, xl, n4);
    }
    tsplit_bf16<<<dim3(D_ / 32, D_ / 32), dim3(32, 8)>>>(Wq, wqh, wql, D_, D_);
    tsplit_bf16<<<dim3(KVW / 32, D_ / 32), dim3(32, 8)>>>(Wk, wkh, wkl, D_, KVW);
    tsplit_bf16<<<dim3(KVW / 32, D_ / 32), dim3(32, 8)>>>(Wv, wvh, wvl, D_, KVW);
    tsplit_bf16<<<dim3(D_ / 32, D_ / 32), dim3(32, 8)>>>(Wo, woh, wol, D_, D_);

    // QKV projections (HMMA bf16x3), fp32 results
    gemm_hmma_x3<<<dim3(D_ / 128, MT / 128), 256, GEMM_SMEM>>>(xh, xl, wqh, wql, q, MT, D_, D_);
    gemm_hmma_x3<<<dim3(KVW / 128, MT / 128), 256, GEMM_SMEM>>>(xh, xl, wkh, wkl, k, MT, KVW, D_);
    gemm_hmma_x3<<<dim3(KVW / 128, MT / 128), 256, GEMM_SMEM>>>(xh, xl, wvh, wvl, v, MT, KVW, D_);

    // RoPE + split q/k; split v
    int nq = MT * H_ * 64, nk = MT * G_ * 64;
    rope_split<<<(nq + 255) / 256, 256>>>(q, qh, ql, H_);
    rope_split<<<(nk + 255) / 256, 256>>>(k, kvh, kvl, G_);
    {
        int n4 = (MT * KVW) / 4;
        split_bf16<<<(n4 + 255) / 256, 256>>>(v, vvh, vvl, n4);
    }

    // HMMA flash attention -> yh/yl (bf16 split)
    attn_hmma<<<dim3(T_ / 128, H_, B_), 256, AT_SMEM>>>(qh, ql, kvh, kvl, vvh, vvl, yh, yl);

    // Output projection (HMMA bf16x3)
    gemm_hmma_x3<<<dim3(D_ / 128, MT / 128), 256, GEMM_SMEM>>>(yh, yl, woh, wol, out, MT, D_, D_);
}